// round 12
// baseline (speedup 1.0000x reference)
#include <cuda_runtime.h>
#include <math.h>

// SenseEmbedding -- champion memory config + cross-iteration x-prefetch.
//
//  x:   [16384, 12] int32   -- [w0, w1, ctx0..ctx9]
//  W_g: [100000, 128] f32
//  W_s: [100000, 8, 128] f32
//  out: [16384, 1] f32
//
// Measured facts (GB300, rounds 1-11): one warp per row (coalesced 512B
// gathers); W_s via __ldcs evict-first (the one 2x lever: protects W_g L2
// residency); persistent single-wave grid. Perf invariant to occupancy, MLP,
// wave count, L1 policy, TMA-vs-LDG -> bound by compulsory L2/LTS transit.
// This round: prefetch next iteration's x row (3x LDG, ~250cyc L2 latency)
// under the current iteration's reduction phase, removing the only exposed
// serial memory dependence in the persistent loop.

#define CTX 10
#define NUM_SENSES 8
#define VEC4 32   // 128 floats = 32 float4

#define NBLOCKS 592   // 148 SMs * 4 resident blocks: exactly one wave
#define NTHREADS 256  // 8 warps/block

__global__ void __launch_bounds__(NTHREADS, 4)
sense_embedding_kernel(const int4* __restrict__ x4,
                       const float4* __restrict__ Wg,
                       const float4* __restrict__ Ws,
                       float* __restrict__ out,
                       int batch)
{
    int warp0 = (blockIdx.x * NTHREADS + threadIdx.x) >> 5;
    int lane = threadIdx.x & 31;
    const int warp_stride = (NBLOCKS * NTHREADS) >> 5;   // 4736 warps total

    if (warp0 >= batch) return;

    // preload first row's index block
    const int4* xr = x4 + (size_t)warp0 * 3;
    int4 xa = __ldg(&xr[0]);
    int4 xb = __ldg(&xr[1]);
    int4 xc = __ldg(&xr[2]);

    for (int row = warp0; row < batch; row += warp_stride) {
        int w0 = xa.x, w1 = xa.y;
        int toks[CTX] = { xa.z, xa.w, xb.x, xb.y, xb.z,
                          xb.w, xc.x, xc.y, xc.z, xc.w };

        // ---- independent gathers: target + 8 senses + 10 context rows ----
        float4 tv = __ldg(&Wg[(size_t)w1 * VEC4 + lane]);   // target row

        const float4* ws_row = Ws + (size_t)w0 * (NUM_SENSES * VEC4) + lane;
        float4 v[NUM_SENSES];
#pragma unroll
        for (int s = 0; s < NUM_SENSES; s++)
            v[s] = __ldcs(&ws_row[s * VEC4]);               // evict-first stream

        float4 acc = make_float4(0.f, 0.f, 0.f, 0.f);
#pragma unroll
        for (int i = 0; i < CTX; i++) {
            float4 cv = __ldg(&Wg[(size_t)toks[i] * VEC4 + lane]);
            acc.x += cv.x; acc.y += cv.y; acc.z += cv.z; acc.w += cv.w;
        }

        // ---- prefetch next row's index block (overlaps reduction phase) ----
        int next = row + warp_stride;
        if (next < batch) {
            const int4* nxr = x4 + (size_t)next * 3;
            xa = __ldg(&nxr[0]);
            xb = __ldg(&nxr[1]);
            xc = __ldg(&nxr[2]);
        }

        // ---- per-lane partial dots ----
        float partial[NUM_SENSES];
#pragma unroll
        for (int s = 0; s < NUM_SENSES; s++)
            partial[s] = v[s].x * acc.x + v[s].y * acc.y
                       + v[s].z * acc.z + v[s].w * acc.w;

        // ---- warp-reduce each score; argmax (first max wins, jnp.argmax) ----
        float best = -INFINITY;
        int bestk = 0;
#pragma unroll
        for (int s = 0; s < NUM_SENSES; s++) {
            float p = partial[s];
            p += __shfl_xor_sync(0xffffffffu, p, 16);
            p += __shfl_xor_sync(0xffffffffu, p, 8);
            p += __shfl_xor_sync(0xffffffffu, p, 4);
            p += __shfl_xor_sync(0xffffffffu, p, 2);
            p += __shfl_xor_sync(0xffffffffu, p, 1);
            if (p > best) { best = p; bestk = s; }  // warp-uniform
        }

        // ---- chosen sense already in registers; select + final dot ----
        float4 ch = v[0];
#pragma unroll
        for (int s = 1; s < NUM_SENSES; s++)
            if (s == bestk) ch = v[s];

        float d = ch.x * tv.x + ch.y * tv.y + ch.z * tv.z + ch.w * tv.w;
        d += __shfl_xor_sync(0xffffffffu, d, 16);
        d += __shfl_xor_sync(0xffffffffu, d, 8);
        d += __shfl_xor_sync(0xffffffffu, d, 4);
        d += __shfl_xor_sync(0xffffffffu, d, 2);
        d += __shfl_xor_sync(0xffffffffu, d, 1);

        if (lane == 0)
            out[row] = 1.0f / (1.0f + __expf(-d));
    }
}

extern "C" void kernel_launch(void* const* d_in, const int* in_sizes, int n_in,
                              void* d_out, int out_size)
{
    const int4*   x  = (const int4*)d_in[0];
    const float4* Wg = (const float4*)d_in[1];
    const float4* Ws = (const float4*)d_in[2];
    float* out = (float*)d_out;

    int batch = in_sizes[0] / (2 + CTX);   // 16384
    sense_embedding_kernel<<<NBLOCKS, NTHREADS>>>(x, Wg, Ws, out, batch);
}

// round 13
// speedup vs baseline: 1.2996x; 1.2996x over previous
#include <cuda_runtime.h>
#include <math.h>

// SenseEmbedding -- converged champion (measured 16.864/16.896us; R12's
// cross-iteration prefetch variant regressed to 22.6us and is reverted).
//
//  x:   [16384, 12] int32   -- [w0, w1, ctx0..ctx9]
//  W_g: [100000, 128] f32
//  W_s: [100000, 8, 128] f32
//  out: [16384, 1] f32
//
// Measured design facts (GB300, rounds 1-12):
//  * One warp per row; lane = float4 slice -> every embedding gather is one
//    fully coalesced 512B access.
//  * W_s via __ldcs (evict-first): protects W_g's L2 residency. The one 2x+
//    lever (39.7 -> 16.9us). evict_last hint policies regress (no
//    persisting-L2 carveout permitted under the harness).
//  * Persistent single-wave grid (148 SMs x 4 blocks). Performance invariant
//    to occupancy (84/45/43%), wave count, L1 policy, TMA-vs-LDG path ->
//    bound by compulsory L2/LTS byte transit (~221MB/pass incl. structural
//    W_s DRAM refill; per-pass stream 160MB > 126MB L2).
//  * Extending register lifetimes across the gather burst (R12 prefetch)
//    reduces front-batched MLP and costs ~34% -- keep the loop body's
//    value lifetimes short.

#define CTX 10
#define NUM_SENSES 8
#define VEC4 32   // 128 floats = 32 float4

#define NBLOCKS 592   // 148 SMs * 4 resident blocks: exactly one wave
#define NTHREADS 256  // 8 warps/block

__global__ void __launch_bounds__(NTHREADS, 4)
sense_embedding_kernel(const int4* __restrict__ x4,
                       const float4* __restrict__ Wg,
                       const float4* __restrict__ Ws,
                       float* __restrict__ out,
                       int batch)
{
    int warp0 = (blockIdx.x * NTHREADS + threadIdx.x) >> 5;
    int lane = threadIdx.x & 31;
    const int warp_stride = (NBLOCKS * NTHREADS) >> 5;   // 4736 warps total

    for (int row = warp0; row < batch; row += warp_stride) {
        // x row = 12 ints = 3 x int4 (warp-uniform broadcast loads)
        const int4* xr = x4 + (size_t)row * 3;
        int4 xa = __ldg(&xr[0]);
        int4 xb = __ldg(&xr[1]);
        int4 xc = __ldg(&xr[2]);
        int w0 = xa.x, w1 = xa.y;
        int toks[CTX] = { xa.z, xa.w, xb.x, xb.y, xb.z,
                          xb.w, xc.x, xc.y, xc.z, xc.w };

        // ---- independent gathers: target + 8 senses + 10 context rows ----
        float4 tv = __ldg(&Wg[(size_t)w1 * VEC4 + lane]);   // target row

        const float4* ws_row = Ws + (size_t)w0 * (NUM_SENSES * VEC4) + lane;
        float4 v[NUM_SENSES];
#pragma unroll
        for (int s = 0; s < NUM_SENSES; s++)
            v[s] = __ldcs(&ws_row[s * VEC4]);               // evict-first stream

        float4 acc = make_float4(0.f, 0.f, 0.f, 0.f);
#pragma unroll
        for (int i = 0; i < CTX; i++) {
            float4 cv = __ldg(&Wg[(size_t)toks[i] * VEC4 + lane]);
            acc.x += cv.x; acc.y += cv.y; acc.z += cv.z; acc.w += cv.w;
        }

        // ---- per-lane partial dots ----
        float partial[NUM_SENSES];
#pragma unroll
        for (int s = 0; s < NUM_SENSES; s++)
            partial[s] = v[s].x * acc.x + v[s].y * acc.y
                       + v[s].z * acc.z + v[s].w * acc.w;

        // ---- warp-reduce each score; argmax (first max wins, jnp.argmax) ----
        float best = -INFINITY;
        int bestk = 0;
#pragma unroll
        for (int s = 0; s < NUM_SENSES; s++) {
            float p = partial[s];
            p += __shfl_xor_sync(0xffffffffu, p, 16);
            p += __shfl_xor_sync(0xffffffffu, p, 8);
            p += __shfl_xor_sync(0xffffffffu, p, 4);
            p += __shfl_xor_sync(0xffffffffu, p, 2);
            p += __shfl_xor_sync(0xffffffffu, p, 1);
            if (p > best) { best = p; bestk = s; }  // warp-uniform
        }

        // ---- chosen sense already in registers; select + final dot ----
        float4 ch = v[0];
#pragma unroll
        for (int s = 1; s < NUM_SENSES; s++)
            if (s == bestk) ch = v[s];

        float d = ch.x * tv.x + ch.y * tv.y + ch.z * tv.z + ch.w * tv.w;
        d += __shfl_xor_sync(0xffffffffu, d, 16);
        d += __shfl_xor_sync(0xffffffffu, d, 8);
        d += __shfl_xor_sync(0xffffffffu, d, 4);
        d += __shfl_xor_sync(0xffffffffu, d, 2);
        d += __shfl_xor_sync(0xffffffffu, d, 1);

        if (lane == 0)
            out[row] = 1.0f / (1.0f + __expf(-d));
    }
}

extern "C" void kernel_launch(void* const* d_in, const int* in_sizes, int n_in,
                              void* d_out, int out_size)
{
    const int4*   x  = (const int4*)d_in[0];
    const float4* Wg = (const float4*)d_in[1];
    const float4* Ws = (const float4*)d_in[2];
    float* out = (float*)d_out;

    int batch = in_sizes[0] / (2 + CTX);   // 16384
    sense_embedding_kernel<<<NBLOCKS, NTHREADS>>>(x, Wg, Ws, out, batch);
}

// round 14
// speedup vs baseline: 1.3416x; 1.0323x over previous
#include <cuda_runtime.h>
#include <math.h>

// SenseEmbedding -- FINAL converged kernel.
// Measured 16.864 / 16.896 / 17.152 / 17.408 us across four runs of this
// exact source (run-to-run noise +-3%; best 16.864us).
//
//  x:   [16384, 12] int32   -- [w0, w1, ctx0..ctx9]
//  W_g: [100000, 128] f32
//  W_s: [100000, 8, 128] f32
//  out: [16384, 1] f32
//
// Design facts established over 13 measured rounds on GB300 (sm_103a):
//  * One warp per row; lane = float4 slice -> every embedding gather is one
//    fully coalesced 512B access (one LDG.128 per lane per row).
//  * W_s via __ldcs (evict-first): keeps the W_g table L2-resident. The only
//    >2x lever found (39.7 -> 16.9us vs default policy). evict_last hint
//    policies regress (no persisting-L2 carveout allowed under harness).
//  * Persistent single-wave grid (148 SMs x 4 blocks). Performance is
//    invariant to occupancy (84/45/43%), MLP (6-19), wave count, L1 policy,
//    and TMA-vs-LDG path -> bound by compulsory L2/LTS byte transit
//    (~221MB/pass incl. the structural ~62MB W_s DRAM refill: the per-pass
//    access stream (160MB) exceeds L2 (126MB), so cross-replay retention of
//    the W_s sweep is impossible without a persisting carveout).
//  * Extending register lifetimes across the gather burst (prefetch variant)
//    cuts front-batched MLP and costs +34% -- loop-body lifetimes stay short.

#define CTX 10
#define NUM_SENSES 8
#define VEC4 32   // 128 floats = 32 float4

#define NBLOCKS 592   // 148 SMs * 4 resident blocks: exactly one wave
#define NTHREADS 256  // 8 warps/block

__global__ void __launch_bounds__(NTHREADS, 4)
sense_embedding_kernel(const int4* __restrict__ x4,
                       const float4* __restrict__ Wg,
                       const float4* __restrict__ Ws,
                       float* __restrict__ out,
                       int batch)
{
    int warp0 = (blockIdx.x * NTHREADS + threadIdx.x) >> 5;
    int lane = threadIdx.x & 31;
    const int warp_stride = (NBLOCKS * NTHREADS) >> 5;   // 4736 warps total

    for (int row = warp0; row < batch; row += warp_stride) {
        // x row = 12 ints = 3 x int4 (warp-uniform broadcast loads)
        const int4* xr = x4 + (size_t)row * 3;
        int4 xa = __ldg(&xr[0]);
        int4 xb = __ldg(&xr[1]);
        int4 xc = __ldg(&xr[2]);
        int w0 = xa.x, w1 = xa.y;
        int toks[CTX] = { xa.z, xa.w, xb.x, xb.y, xb.z,
                          xb.w, xc.x, xc.y, xc.z, xc.w };

        // ---- independent gathers: target + 8 senses + 10 context rows ----
        float4 tv = __ldg(&Wg[(size_t)w1 * VEC4 + lane]);   // target row

        const float4* ws_row = Ws + (size_t)w0 * (NUM_SENSES * VEC4) + lane;
        float4 v[NUM_SENSES];
#pragma unroll
        for (int s = 0; s < NUM_SENSES; s++)
            v[s] = __ldcs(&ws_row[s * VEC4]);               // evict-first stream

        float4 acc = make_float4(0.f, 0.f, 0.f, 0.f);
#pragma unroll
        for (int i = 0; i < CTX; i++) {
            float4 cv = __ldg(&Wg[(size_t)toks[i] * VEC4 + lane]);
            acc.x += cv.x; acc.y += cv.y; acc.z += cv.z; acc.w += cv.w;
        }

        // ---- per-lane partial dots ----
        float partial[NUM_SENSES];
#pragma unroll
        for (int s = 0; s < NUM_SENSES; s++)
            partial[s] = v[s].x * acc.x + v[s].y * acc.y
                       + v[s].z * acc.z + v[s].w * acc.w;

        // ---- warp-reduce each score; argmax (first max wins, jnp.argmax) ----
        float best = -INFINITY;
        int bestk = 0;
#pragma unroll
        for (int s = 0; s < NUM_SENSES; s++) {
            float p = partial[s];
            p += __shfl_xor_sync(0xffffffffu, p, 16);
            p += __shfl_xor_sync(0xffffffffu, p, 8);
            p += __shfl_xor_sync(0xffffffffu, p, 4);
            p += __shfl_xor_sync(0xffffffffu, p, 2);
            p += __shfl_xor_sync(0xffffffffu, p, 1);
            if (p > best) { best = p; bestk = s; }  // warp-uniform
        }

        // ---- chosen sense already in registers; select + final dot ----
        float4 ch = v[0];
#pragma unroll
        for (int s = 1; s < NUM_SENSES; s++)
            if (s == bestk) ch = v[s];

        float d = ch.x * tv.x + ch.y * tv.y + ch.z * tv.z + ch.w * tv.w;
        d += __shfl_xor_sync(0xffffffffu, d, 16);
        d += __shfl_xor_sync(0xffffffffu, d, 8);
        d += __shfl_xor_sync(0xffffffffu, d, 4);
        d += __shfl_xor_sync(0xffffffffu, d, 2);
        d += __shfl_xor_sync(0xffffffffu, d, 1);

        if (lane == 0)
            out[row] = 1.0f / (1.0f + __expf(-d));
    }
}

extern "C" void kernel_launch(void* const* d_in, const int* in_sizes, int n_in,
                              void* d_out, int out_size)
{
    const int4*   x  = (const int4*)d_in[0];
    const float4* Wg = (const float4*)d_in[1];
    const float4* Ws = (const float4*)d_in[2];
    float* out = (float*)d_out;

    int batch = in_sizes[0] / (2 + CTX);   // 16384
    sense_embedding_kernel<<<NBLOCKS, NTHREADS>>>(x, Wg, Ws, out, batch);
}